// round 11
// baseline (speedup 1.0000x reference)
#include <cuda_runtime.h>
#include <math.h>

// ---------------------------------------------------------------------------
// EncoderGRUODE: B=256, T=512, D_IN=64, H=128
// 128 CTAs x 512 threads (16 warps). Thread (i = wrp*8 + (lane&7), kq = lane>>3)
// owns element i of BOTH rows; computes k-quarter kq of every dot product.
// 4-way reduction = shfl_xor(8) + shfl_xor(16) (kq lives in lane bits 3:4).
// W_node + W_ih quarters in registers; W_hh (3 gates) in SMEM; W_out from L2.
// 6 barriers/step. All dots use fma.rn.f32x2 (FFMA2).
// ---------------------------------------------------------------------------

#define B_   256
#define T_   512
#define DIN  64
#define H_   128

typedef unsigned long long ull;

// packed weights produced by prep_kernel
__device__ float4 g_whh4[12288];   // [0:4096) R | [4096:8192) Z | [8192:12288) N ; idx=(k/4)*128+i
__device__ float4 g_wout4[2048];   // (k/4)*64 + j -> {W_out[j][k..k+3]}
__device__ int    g_mask[T_];
__device__ float  g_dt[T_];

// ---------------------------------------------------------------------------
__global__ void prep_kernel(const float* __restrict__ W_hh,
                            const float* __restrict__ W_out,
                            const unsigned char* __restrict__ mask_raw,
                            const float* __restrict__ tp)
{
    int gtid = blockIdx.x * blockDim.x + threadIdx.x;
    int nthr = gridDim.x * blockDim.x;

    for (int idx = gtid; idx < 4096; idx += nthr) {
        int kq = idx >> 7, i = idx & 127, k = kq * 4;
        g_whh4[idx] = make_float4(W_hh[i * H_ + k],     W_hh[i * H_ + k + 1],
                                  W_hh[i * H_ + k + 2], W_hh[i * H_ + k + 3]);
        int iz = H_ + i;
        g_whh4[4096 + idx] = make_float4(W_hh[iz * H_ + k],     W_hh[iz * H_ + k + 1],
                                         W_hh[iz * H_ + k + 2], W_hh[iz * H_ + k + 3]);
        int in_ = 2 * H_ + i;
        g_whh4[8192 + idx] = make_float4(W_hh[in_ * H_ + k],     W_hh[in_ * H_ + k + 1],
                                         W_hh[in_ * H_ + k + 2], W_hh[in_ * H_ + k + 3]);
    }
    for (int idx = gtid; idx < 2048; idx += nthr) {
        int kq = idx >> 6, j = idx & 63, k = kq * 4;
        g_wout4[idx] = make_float4(W_out[j * H_ + k],     W_out[j * H_ + k + 1],
                                   W_out[j * H_ + k + 2], W_out[j * H_ + k + 3]);
    }
    if (gtid < T_)
        g_dt[gtid] = (gtid == 0) ? 0.01f : (tp[gtid] - tp[gtid - 1]);

    // robust mask decode (uint8 / int32 / float32) — unchanged (passed R5-R9)
    if (blockIdx.x == 0 && threadIdx.x == 0) {
        bool nz_nonmult = false, one_mult = false, f32_sig = true;
        for (int i = 0; i < T_; i++) {
            unsigned char v = mask_raw[i];
            int m4 = i & 3;
            if (m4 != 0 && v) nz_nonmult = true;
            if (m4 == 0 && v == 1) one_mult = true;
            if (m4 == 0 || m4 == 1) { if (v != 0) f32_sig = false; }
            else if (m4 == 2)       { if (v != 0 && v != 0x80) f32_sig = false; }
            else                    { if (v != 0 && v != 0x3F) f32_sig = false; }
        }
        if (!nz_nonmult && one_mult) {
            const int* mi = (const int*)mask_raw;
            for (int i = 0; i < T_; i++) g_mask[i] = (mi[i] != 0);
        } else if (nz_nonmult && f32_sig) {
            const float* mf = (const float*)mask_raw;
            for (int i = 0; i < T_; i++) g_mask[i] = (mf[i] != 0.0f);
        } else {
            for (int i = 0; i < T_; i++) g_mask[i] = (mask_raw[i] != 0);
        }
    }
}

// ---------------------------------------------------------------------------
// SMEM layout (float offsets)
#define RS        132
#define SMF_WHH   0        // 49152: R | Z | N as float4 idx=(k/4)*128+i (192 KB)
#define SMF_A     49152    // 264: h       [row*RS + k]
#define SMF_B     49416    // 264: RK4 scratch
#define SMF_C     49680    // 264: RK4 scratch (XO aliases; disjoint lifetime)
#define SMF_XO    SMF_C    // 256: out-proj partials [row*128 + b*64 + j]
#define SMF_HO    49944    // 264: h_ode
#define SMF_INP   50208    // 136: inp [row*68 + j]
#define SMF_PO    50344    // 128: prev_out [row*64 + j]
#define SMF_BIAS  50472    // 512: bs_r | bs_z | bihn | bhhn (each 128)
#define SMF_BO    50984    // 64
#define SMF_DT    51048    // 512
#define SMF_MSK   51560    // 512 (ints)
#define SMF_TOT   52072
#define SMEM_BYTES (SMF_TOT * 4)   // 208288 B

__device__ __forceinline__ void fma2(ull& acc, ull a, ull b) {
    asm("fma.rn.f32x2 %0, %1, %2, %0;" : "+l"(acc) : "l"(a), "l"(b));
}
__device__ __forceinline__ float psum(ull a) {
    float2 f = *reinterpret_cast<float2*>(&a);
    return f.x + f.y;
}
__device__ __forceinline__ float tanh_fast(float x) {
    float y;
    asm("tanh.approx.f32 %0, %1;" : "=f"(y) : "f"(x));
    return y;
}
__device__ __forceinline__ float sig_fast(float x) {
    return fmaf(0.5f, tanh_fast(0.5f * x), 0.5f);
}
__device__ __forceinline__ float red4(float p) {   // sum over kq (lane bits 3:4)
    p += __shfl_xor_sync(0xffffffffu, p, 8);
    p += __shfl_xor_sync(0xffffffffu, p, 16);
    return p;
}

__global__ void __launch_bounds__(512, 1)
enc_gruode_kernel(const float* __restrict__ x,
                  const float* __restrict__ W_ih,
                  const float* __restrict__ b_ih,
                  const float* __restrict__ b_hh,
                  const float* __restrict__ W_node,
                  const float* __restrict__ b_node,
                  const float* __restrict__ b_out,
                  float* __restrict__ out)
{
    extern __shared__ float sm[];
    int* smi = (int*)sm;
    const int tid  = threadIdx.x;
    const int lane = tid & 31;
    const int wrp  = tid >> 5;
    const int kq   = lane >> 3;                 // k-quarter (lane bits 3:4)
    const int i    = (wrp << 3) | (lane & 7);   // my element

    // ---- stage W_hh (3 gates) into SMEM ----
    {
        float4* d = (float4*)sm;
        for (int idx = tid; idx < 12288; idx += 512) d[idx] = g_whh4[idx];
    }
    for (int idx = tid; idx < 512; idx += 512) { }   // (no-op placeholder)
    if (tid < 512) {
        sm[SMF_DT + tid]   = g_dt[tid];
        smi[SMF_MSK + tid] = g_mask[tid];
    }
    if (tid < 264) sm[SMF_A + tid] = 0.0f;
    if (tid < 128) {
        sm[SMF_PO + tid] = b_out[tid & 63];     // prev_out at t=0 (h0=0)
        sm[SMF_BIAS + tid]       = b_ih[tid]       + b_hh[tid];        // bs_r
        sm[SMF_BIAS + 128 + tid] = b_ih[128 + tid] + b_hh[128 + tid];  // bs_z
        sm[SMF_BIAS + 256 + tid] = b_ih[256 + tid];                    // bihn
        sm[SMF_BIAS + 384 + tid] = b_hh[256 + tid];                    // bhhn
    }
    if (tid < 64) sm[SMF_BO + tid] = b_out[tid];

    // ---- register weights (k-quarter, packed as ull) ----
    ull wn2[16];                   // W_node[i][32*kq .. +32)
    {
        const ulonglong2* ws = (const ulonglong2*)(W_node + (size_t)i * H_ + 32 * kq);
#pragma unroll
        for (int q = 0; q < 8; q++) { ulonglong2 v = ws[q]; wn2[2*q] = v.x; wn2[2*q+1] = v.y; }
    }
    ull wr2[8], wz2[8], wm2[8];    // W_ih rows r,z,n over k in [16*kq, +16)
    {
        const ulonglong2* sr = (const ulonglong2*)(W_ih + (size_t)i * DIN + 16 * kq);
        const ulonglong2* sz = (const ulonglong2*)(W_ih + (size_t)(H_ + i) * DIN + 16 * kq);
        const ulonglong2* sn = (const ulonglong2*)(W_ih + (size_t)(2 * H_ + i) * DIN + 16 * kq);
#pragma unroll
        for (int q = 0; q < 4; q++) {
            ulonglong2 a = sr[q]; wr2[2*q] = a.x; wr2[2*q+1] = a.y;
            ulonglong2 b = sz[q]; wz2[2*q] = b.x; wz2[2*q+1] = b.y;
            ulonglong2 c = sn[q]; wm2[2*q] = c.x; wm2[2*q+1] = c.y;
        }
    }

    const float bn_i = b_node[i];
    const float bo   = (tid < 128) ? b_out[tid & 63] : 0.0f;

    // x / out pointers for the tid<128 role (row = tid>>6, j = tid&63)
    const float* xr   = x   + (size_t)(2 * blockIdx.x + (tid >> 6)) * T_ * DIN + (tid & 63);
    float*       orow = out + (size_t)(2 * blockIdx.x + (tid >> 6)) * T_ * DIN + (tid & 63);

    __syncthreads();

    float hreg0 = 0.0f, hreg1 = 0.0f;
    float xv = (tid < 128) ? __ldg(xr) : 0.0f;   // prefetch x[t=0]

    const ulonglong2* W2  = (const ulonglong2*)sm;       // W_hh: R 0 | Z +4096 | N +8192
    const ulonglong2* WOg = (const ulonglong2*)g_wout4;  // L2-resident

    // RK4 matvec: quarter-dots for both rows + two-shuffle reduction
    auto STAGE = [&](const float* buf, float& d0, float& d1) {
        const ulonglong2* U = (const ulonglong2*)(buf + 32 * kq);
        const ulonglong2* V = (const ulonglong2*)(buf + RS + 32 * kq);
        ull a0 = 0, a1 = 0, c0 = 0, c1 = 0;
#pragma unroll
        for (int q = 0; q < 8; q++) {
            ulonglong2 u = U[q], v = V[q];
            fma2(a0, wn2[2*q], u.x); fma2(a1, wn2[2*q+1], u.y);
            fma2(c0, wn2[2*q], v.x); fma2(c1, wn2[2*q+1], v.y);
        }
        d0 = red4(psum(a0) + psum(a1)) + bn_i;
        d1 = red4(psum(c0) + psum(c1)) + bn_i;
    };

    for (int t = 0; t < T_; ++t) {
        const float dt  = sm[SMF_DT + t];
        const int   msk = smi[SMF_MSK + t];
        const float hdt = 0.5f * dt;

        float d0, d1, kv0, kv1;

        // ---- RK4 stage 1: read A -> write B ----
        STAGE(sm + SMF_A, d0, d1);
        kv0 = tanh_fast(d0); kv1 = tanh_fast(d1);
        float ksum0 = kv0, ksum1 = kv1;
        if (kq == 0) sm[SMF_B + i]      = fmaf(hdt, kv0, hreg0);
        if (kq == 1) sm[SMF_B + RS + i] = fmaf(hdt, kv1, hreg1);
        __syncthreads();                                             // B1

        // input staging (PO ordered by B1); prefetch next x
        if (tid < 128) {
            sm[SMF_INP + (tid >> 6) * 68 + (tid & 63)] = msk ? xv : sm[SMF_PO + tid];
            if (t + 1 < T_) xv = __ldg(xr + (size_t)(t + 1) * DIN);
        }

        // ---- RK4 stage 2: read B -> write C ----
        STAGE(sm + SMF_B, d0, d1);
        kv0 = tanh_fast(d0); kv1 = tanh_fast(d1);
        ksum0 = fmaf(2.0f, kv0, ksum0); ksum1 = fmaf(2.0f, kv1, ksum1);
        if (kq == 0) sm[SMF_C + i]      = fmaf(hdt, kv0, hreg0);
        if (kq == 1) sm[SMF_C + RS + i] = fmaf(hdt, kv1, hreg1);
        __syncthreads();                                             // B2

        // ---- i-gate quarter-dots (INP visible post-B2), reduced via shuffles ----
        float irT0, irT1, izT0, izT1, inT0, inT1;
        {
            const ulonglong2* IU = (const ulonglong2*)(sm + SMF_INP + 16 * kq);
            const ulonglong2* IV = (const ulonglong2*)(sm + SMF_INP + 68 + 16 * kq);
            ull ar = 0, az = 0, an = 0, br = 0, bz = 0, bn2 = 0;
#pragma unroll
            for (int q = 0; q < 4; q++) {
                ulonglong2 u = IU[q], v = IV[q];
                fma2(ar, wr2[2*q], u.x); fma2(ar, wr2[2*q+1], u.y);
                fma2(az, wz2[2*q], u.x); fma2(az, wz2[2*q+1], u.y);
                fma2(an, wm2[2*q], u.x); fma2(an, wm2[2*q+1], u.y);
                fma2(br, wr2[2*q], v.x); fma2(br, wr2[2*q+1], v.y);
                fma2(bz, wz2[2*q], v.x); fma2(bz, wz2[2*q+1], v.y);
                fma2(bn2, wm2[2*q], v.x); fma2(bn2, wm2[2*q+1], v.y);
            }
            irT0 = red4(psum(ar));  irT1 = red4(psum(br));
            izT0 = red4(psum(az));  izT1 = red4(psum(bz));
            inT0 = red4(psum(an));  inT1 = red4(psum(bn2));
        }

        // ---- RK4 stage 3: read C -> write B ----
        STAGE(sm + SMF_C, d0, d1);
        kv0 = tanh_fast(d0); kv1 = tanh_fast(d1);
        ksum0 = fmaf(2.0f, kv0, ksum0); ksum1 = fmaf(2.0f, kv1, ksum1);
        if (kq == 0) sm[SMF_B + i]      = fmaf(dt, kv0, hreg0);
        if (kq == 1) sm[SMF_B + RS + i] = fmaf(dt, kv1, hreg1);
        __syncthreads();                                             // B3

        // ---- RK4 stage 4: read B -> h_ode ----
        STAGE(sm + SMF_B, d0, d1);
        kv0 = tanh_fast(d0); kv1 = tanh_fast(d1);
        const float c6 = dt * (1.0f / 6.0f);
        const float hode0 = fmaf(c6, ksum0 + kv0, hreg0);
        const float hode1 = fmaf(c6, ksum1 + kv1, hreg1);
        if (kq == 0) sm[SMF_HO + i]      = hode0;
        if (kq == 1) sm[SMF_HO + RS + i] = hode1;
        __syncthreads();                                             // B4

        // ---- GRU W_hh quarter-dots (SMEM) + shuffle reduce + gate combine ----
        {
            const ulonglong2* HU = (const ulonglong2*)(sm + SMF_HO + 32 * kq);
            const ulonglong2* HV = (const ulonglong2*)(sm + SMF_HO + RS + 32 * kq);
            ull R0 = 0, R1 = 0, Z0 = 0, Z1 = 0, N0 = 0, N1 = 0;
#pragma unroll
            for (int q = 0; q < 8; q++) {
                const int idx = (8 * kq + q) * 128 + i;
                ulonglong2 wr = W2[idx];
                ulonglong2 wz = W2[4096 + idx];
                ulonglong2 wn = W2[8192 + idx];
                ulonglong2 u = HU[q], v = HV[q];
                fma2(R0, wr.x, u.x); fma2(R0, wr.y, u.y);
                fma2(R1, wr.x, v.x); fma2(R1, wr.y, v.y);
                fma2(Z0, wz.x, u.x); fma2(Z0, wz.y, u.y);
                fma2(Z1, wz.x, v.x); fma2(Z1, wz.y, v.y);
                fma2(N0, wn.x, u.x); fma2(N0, wn.y, u.y);
                fma2(N1, wn.x, v.x); fma2(N1, wn.y, v.y);
            }
            float hrT0 = red4(psum(R0)), hrT1 = red4(psum(R1));
            float hzT0 = red4(psum(Z0)), hzT1 = red4(psum(Z1));
            float hnT0 = red4(psum(N0)), hnT1 = red4(psum(N1));

            const float bsr = sm[SMF_BIAS + i];
            const float bsz = sm[SMF_BIAS + 128 + i];
            const float bin = sm[SMF_BIAS + 256 + i];
            const float bhn = sm[SMF_BIAS + 384 + i];

            float rr0 = sig_fast(irT0 + hrT0 + bsr);
            float zz0 = sig_fast(izT0 + hzT0 + bsz);
            float nn0 = tanh_fast(inT0 + bin + rr0 * (hnT0 + bhn));
            hreg0 = nn0 + zz0 * (hode0 - nn0);

            float rr1 = sig_fast(irT1 + hrT1 + bsr);
            float zz1 = sig_fast(izT1 + hzT1 + bsz);
            float nn1 = tanh_fast(inT1 + bin + rr1 * (hnT1 + bhn));
            hreg1 = nn1 + zz1 * (hode1 - nn1);

            if (kq == 0) sm[SMF_A + i]      = hreg0;
            if (kq == 1) sm[SMF_A + RS + i] = hreg1;
        }
        __syncthreads();                                             // B5

        // ---- output projection: k-eighth = (kq<<1)|(i>>6), j = i&63, both rows ----
        {
            const int j = i & 63, b_ = i >> 6, e8 = (kq << 1) | b_;
            const ulonglong2* S0 = (const ulonglong2*)(sm + SMF_A + 16 * e8);
            const ulonglong2* S1 = (const ulonglong2*)(sm + SMF_A + RS + 16 * e8);
            ull o0 = 0, o1 = 0;
#pragma unroll
            for (int q = 0; q < 4; q++) {
                ulonglong2 w = WOg[(size_t)(4 * e8 + q) * 64 + j];
                ulonglong2 s0 = S0[q], s1 = S1[q];
                fma2(o0, w.x, s0.x); fma2(o0, w.y, s0.y);
                fma2(o1, w.x, s1.x); fma2(o1, w.y, s1.y);
            }
            float p0 = red4(psum(o0));     // sums over kq -> half-k partial per b_
            float p1 = red4(psum(o1));
            if (kq == 0) {
                sm[SMF_XO + b_ * 64 + j]       = p0;
                sm[SMF_XO + 128 + b_ * 64 + j] = p1;
            }
        }
        __syncthreads();                                             // B6

        // ---- output combine (also next step's prev_out); next B1 orders PO ----
        if (tid < 128) {
            const int base = SMF_XO + (tid >> 6) * 128 + (tid & 63);
            float y = sm[base] + sm[base + 64] + bo;
            orow[(size_t)t * DIN] = y;
            sm[SMF_PO + tid] = y;
        }
    }
}

// ---------------------------------------------------------------------------
extern "C" void kernel_launch(void* const* d_in, const int* in_sizes, int n_in,
                              void* d_out, int out_size)
{
    const float*         x      = (const float*)d_in[0];
    const float*         tp     = (const float*)d_in[1];
    const unsigned char* mask   = (const unsigned char*)d_in[2];
    const float*         W_ih   = (const float*)d_in[3];
    const float*         W_hh   = (const float*)d_in[4];
    const float*         b_ih   = (const float*)d_in[5];
    const float*         b_hh   = (const float*)d_in[6];
    const float*         W_node = (const float*)d_in[7];
    const float*         b_node = (const float*)d_in[8];
    const float*         W_out  = (const float*)d_in[9];
    const float*         b_out  = (const float*)d_in[10];
    float*               out    = (float*)d_out;

    prep_kernel<<<32, 256>>>(W_hh, W_out, mask, tp);

    cudaFuncSetAttribute(enc_gruode_kernel,
                         cudaFuncAttributeMaxDynamicSharedMemorySize,
                         SMEM_BYTES);
    enc_gruode_kernel<<<B_ / 2, 512, SMEM_BYTES>>>(
        x, W_ih, b_ih, b_hh, W_node, b_node, b_out, out);
}

// round 12
// speedup vs baseline: 1.4796x; 1.4796x over previous
#include <cuda_runtime.h>
#include <math.h>

// ---------------------------------------------------------------------------
// EncoderGRUODE: B=256, T=512, D_IN=64, H=128
// 128 CTAs x 256 threads (R8 shape). Thread (half = lane>>4, i = 16*wrp+lane&15)
// owns element i of row `half`, computes k-half `half` of every dot.
// Half-exchange via shfl_xor(16). All dots use fma.rn.f32x2 (FFMA2).
// W_node + W_ih in regs; W_hh (3 gates) in SMEM; W_out streamed from L2/L1.
// 5 barriers/step: out-projection folded into the stage-1 phase; prev_out
// lives in a register (no PO buffer).
// ---------------------------------------------------------------------------

#define B_   256
#define T_   512
#define DIN  64
#define H_   128

typedef unsigned long long ull;

// packed weights produced by prep_kernel
__device__ float4 g_whh4[12288];   // [0:4096) R | [4096:8192) Z | [8192:12288) N ; idx=(k/4)*128+i
__device__ float4 g_wout4[2048];   // (k/4)*64 + j -> {W_out[j][k..k+3]}
__device__ int    g_mask[T_];
__device__ float  g_dt[T_];

// ---------------------------------------------------------------------------
__global__ void prep_kernel(const float* __restrict__ W_hh,
                            const float* __restrict__ W_out,
                            const unsigned char* __restrict__ mask_raw,
                            const float* __restrict__ tp)
{
    int gtid = blockIdx.x * blockDim.x + threadIdx.x;
    int nthr = gridDim.x * blockDim.x;

    for (int idx = gtid; idx < 4096; idx += nthr) {
        int kq = idx >> 7, i = idx & 127, k = kq * 4;
        g_whh4[idx] = make_float4(W_hh[i * H_ + k],     W_hh[i * H_ + k + 1],
                                  W_hh[i * H_ + k + 2], W_hh[i * H_ + k + 3]);
        int iz = H_ + i;
        g_whh4[4096 + idx] = make_float4(W_hh[iz * H_ + k],     W_hh[iz * H_ + k + 1],
                                         W_hh[iz * H_ + k + 2], W_hh[iz * H_ + k + 3]);
        int in_ = 2 * H_ + i;
        g_whh4[8192 + idx] = make_float4(W_hh[in_ * H_ + k],     W_hh[in_ * H_ + k + 1],
                                         W_hh[in_ * H_ + k + 2], W_hh[in_ * H_ + k + 3]);
    }
    for (int idx = gtid; idx < 2048; idx += nthr) {
        int kq = idx >> 6, j = idx & 63, k = kq * 4;
        g_wout4[idx] = make_float4(W_out[j * H_ + k],     W_out[j * H_ + k + 1],
                                   W_out[j * H_ + k + 2], W_out[j * H_ + k + 3]);
    }
    if (gtid < T_)
        g_dt[gtid] = (gtid == 0) ? 0.01f : (tp[gtid] - tp[gtid - 1]);

    // robust mask decode (uint8 / int32 / float32) — unchanged (passed R5-R11)
    if (blockIdx.x == 0 && threadIdx.x == 0) {
        bool nz_nonmult = false, one_mult = false, f32_sig = true;
        for (int i = 0; i < T_; i++) {
            unsigned char v = mask_raw[i];
            int m4 = i & 3;
            if (m4 != 0 && v) nz_nonmult = true;
            if (m4 == 0 && v == 1) one_mult = true;
            if (m4 == 0 || m4 == 1) { if (v != 0) f32_sig = false; }
            else if (m4 == 2)       { if (v != 0 && v != 0x80) f32_sig = false; }
            else                    { if (v != 0 && v != 0x3F) f32_sig = false; }
        }
        if (!nz_nonmult && one_mult) {
            const int* mi = (const int*)mask_raw;
            for (int i = 0; i < T_; i++) g_mask[i] = (mi[i] != 0);
        } else if (nz_nonmult && f32_sig) {
            const float* mf = (const float*)mask_raw;
            for (int i = 0; i < T_; i++) g_mask[i] = (mf[i] != 0.0f);
        } else {
            for (int i = 0; i < T_; i++) g_mask[i] = (mask_raw[i] != 0);
        }
    }
}

// ---------------------------------------------------------------------------
// SMEM layout (float offsets). Row stride 132 on state buffers.
#define RS       132
#define SMF_WHH  0        // 49152 floats (R|Z|N as float4, idx=(k/4)*128+i)
#define SMF_A    49152    // 264: h      [row*RS + k]
#define SMF_B    49416    // 264: RK4 scratch
#define SMF_C    49680    // 264: RK4 scratch
#define SMF_HO   49944    // 264: h_ode
#define SMF_INP  50208    // 136: inp [row*68 + j]
#define SMF_XO   50344    // 512: out-proj partials [row*256 + kq*64 + j]
#define SMF_TOT  50856
#define SMEM_BYTES (SMF_TOT * 4)   // 203424 B

__device__ __forceinline__ void fma2(ull& acc, ull a, ull b) {
    asm("fma.rn.f32x2 %0, %1, %2, %0;" : "+l"(acc) : "l"(a), "l"(b));
}
__device__ __forceinline__ float psum(ull a) {
    float2 f = *reinterpret_cast<float2*>(&a);
    return f.x + f.y;
}
__device__ __forceinline__ float tanh_fast(float x) {
    float y;
    asm("tanh.approx.f32 %0, %1;" : "=f"(y) : "f"(x));
    return y;
}
__device__ __forceinline__ float sig_fast(float x) {
    return fmaf(0.5f, tanh_fast(0.5f * x), 0.5f);
}

__global__ void __launch_bounds__(256, 1)
enc_gruode_kernel(const float* __restrict__ x,
                  const float* __restrict__ b_ih,
                  const float* __restrict__ b_hh,
                  const float* __restrict__ W_ih,
                  const float* __restrict__ W_node,
                  const float* __restrict__ b_node,
                  const float* __restrict__ b_out,
                  float* __restrict__ out)
{
    extern __shared__ float sm[];
    const int tid  = threadIdx.x;
    const int lane = tid & 31;
    const int wrp  = tid >> 5;
    const int half = lane >> 4;                 // k-half AND my row
    const int i    = (wrp << 4) | (lane & 15);  // my element

    // ---- stage packed W_hh into SMEM ----
    {
        float4* d = (float4*)sm;
        for (int idx = tid; idx < 12288; idx += 256) d[idx] = g_whh4[idx];
    }
    for (int idx = tid; idx < 264; idx += 256) sm[SMF_A + idx] = 0.0f;

    // ---- register weights, k-pair packed as ull ----
    ull wn2[32];                     // W_node[i][64*half .. +64)
    {
        const ulonglong2* ws = (const ulonglong2*)(W_node + (size_t)i * H_ + 64 * half);
#pragma unroll
        for (int q = 0; q < 16; q++) { ulonglong2 v = ws[q]; wn2[2*q] = v.x; wn2[2*q+1] = v.y; }
    }
    ull wr2[16], wz2[16], wm2[16];   // W_ih rows r,z,n over k in [32*half, +32)
    {
        const ulonglong2* sr = (const ulonglong2*)(W_ih + (size_t)i * DIN + 32 * half);
        const ulonglong2* sz = (const ulonglong2*)(W_ih + (size_t)(H_ + i) * DIN + 32 * half);
        const ulonglong2* sn = (const ulonglong2*)(W_ih + (size_t)(2 * H_ + i) * DIN + 32 * half);
#pragma unroll
        for (int q = 0; q < 8; q++) {
            ulonglong2 a = sr[q]; wr2[2*q] = a.x; wr2[2*q+1] = a.y;
            ulonglong2 b = sz[q]; wz2[2*q] = b.x; wz2[2*q+1] = b.y;
            ulonglong2 c = sn[q]; wm2[2*q] = c.x; wm2[2*q+1] = c.y;
        }
    }

    // combiner constants (thread is combiner for (row=half, elem=i))
    const float bn_i = b_node[i];
    const float bs_r = b_ih[i]       + b_hh[i];
    const float bs_z = b_ih[128 + i] + b_hh[128 + i];
    const float bihn = b_ih[256 + i];
    const float bhhn = b_hh[256 + i];
    const float bo   = (tid < 128) ? b_out[tid & 63] : 0.0f;

    // x / out pointers for the tid<128 role (row = tid>>6, j = tid&63)
    const float* xr   = x   + (size_t)(2 * blockIdx.x + (tid >> 6)) * T_ * DIN + (tid & 63);
    float*       orow = out + (size_t)(2 * blockIdx.x + (tid >> 6)) * T_ * DIN + (tid & 63);

    __syncthreads();

    float hreg = 0.0f;
    float y    = 0.0f;                            // prev_out kept in register
    float xv   = (tid < 128) ? __ldg(xr) : 0.0f;  // prefetch x[t=0]

    // one RK4 matvec: full dot for my row via half-dot + shfl_xor(16)
    auto STAGE = [&](const float* buf) -> float {
        const ulonglong2* U = (const ulonglong2*)(buf + 64 * half);
        const ulonglong2* V = (const ulonglong2*)(buf + RS + 64 * half);
        ull a0 = 0, a1 = 0, c0 = 0, c1 = 0;
#pragma unroll
        for (int q = 0; q < 16; q++) {
            ulonglong2 u = U[q], v = V[q];
            fma2(a0, wn2[2*q], u.x); fma2(a1, wn2[2*q+1], u.y);
            fma2(c0, wn2[2*q], v.x); fma2(c1, wn2[2*q+1], v.y);
        }
        float p0 = psum(a0) + psum(a1);          // row0 partial, my k-half
        float p1 = psum(c0) + psum(c1);          // row1 partial
        float mine = half ? p1 : p0;
        float oth  = __shfl_xor_sync(0xffffffffu, half ? p0 : p1, 16);
        return mine + oth + bn_i;
    };

    // out-projection partials from buffer A (j = i&63, k-quarter kq, BOTH rows)
    auto OUTPROJ = [&]() {
        const int j = i & 63, kq = (i >> 6) | (half << 1);
        const ulonglong2* S0 = (const ulonglong2*)(sm + SMF_A + 32 * kq);
        const ulonglong2* S1 = (const ulonglong2*)(sm + SMF_A + RS + 32 * kq);
        const ulonglong2* WOg = (const ulonglong2*)g_wout4;
        ull o0 = 0, o1 = 0;
#pragma unroll
        for (int q = 0; q < 8; q++) {
            ulonglong2 w = WOg[(size_t)(8 * kq + q) * 64 + j];
            ulonglong2 s0 = S0[q], s1 = S1[q];
            fma2(o0, w.x, s0.x); fma2(o0, w.y, s0.y);
            fma2(o1, w.x, s1.x); fma2(o1, w.y, s1.y);
        }
        sm[SMF_XO + kq * 64 + j]       = psum(o0);
        sm[SMF_XO + 256 + kq * 64 + j] = psum(o1);
    };

    for (int t = 0; t < T_; ++t) {
        const float dt  = __ldg(g_dt + t);
        const int   msk = __ldg(g_mask + t);
        const float hdt = 0.5f * dt;

        // ---- P0: out-projection of h(t-1) + RK4 stage 1 (both read A) ----
        OUTPROJ();
        float kv = tanh_fast(STAGE(sm + SMF_A));
        float ksum = kv;
        sm[SMF_B + half * RS + i] = fmaf(hdt, kv, hreg);
        __syncthreads();                                             // B1

        // ---- P1: y combine + out store + INP staging ; RK4 stage 2 ----
        if (tid < 128) {
            const int base = SMF_XO + (tid >> 6) * 256 + (tid & 63);
            y = sm[base] + sm[base + 64] + sm[base + 128] + sm[base + 192] + bo;
            if (t) orow[(size_t)(t - 1) * DIN] = y;      // out[t-1]
            sm[SMF_INP + (tid >> 6) * 68 + (tid & 63)] = msk ? xv : y;
            if (t + 1 < T_) xv = __ldg(xr + (size_t)(t + 1) * DIN);
        }
        kv = tanh_fast(STAGE(sm + SMF_B));
        ksum = fmaf(2.0f, kv, ksum);
        sm[SMF_C + half * RS + i] = fmaf(hdt, kv, hreg);
        __syncthreads();                                             // B2

        // ---- P2: i-gate dots (INP visible) ; RK4 stage 3 ----
        float irT, izT, inT;
        {
            const ulonglong2* IU = (const ulonglong2*)(sm + SMF_INP + 32 * half);
            const ulonglong2* IV = (const ulonglong2*)(sm + SMF_INP + 68 + 32 * half);
            ull ar = 0, az = 0, an = 0, br = 0, bz = 0, bn2 = 0;
#pragma unroll
            for (int q = 0; q < 8; q++) {
                ulonglong2 u = IU[q], v = IV[q];
                fma2(ar, wr2[2*q], u.x); fma2(ar, wr2[2*q+1], u.y);
                fma2(az, wz2[2*q], u.x); fma2(az, wz2[2*q+1], u.y);
                fma2(an, wm2[2*q], u.x); fma2(an, wm2[2*q+1], u.y);
                fma2(br, wr2[2*q], v.x); fma2(br, wr2[2*q+1], v.y);
                fma2(bz, wz2[2*q], v.x); fma2(bz, wz2[2*q+1], v.y);
                fma2(bn2, wm2[2*q], v.x); fma2(bn2, wm2[2*q+1], v.y);
            }
            float r0 = psum(ar), r1 = psum(br);
            float z0 = psum(az), z1 = psum(bz);
            float n0 = psum(an), n1 = psum(bn2);
            irT = (half ? r1 : r0) + __shfl_xor_sync(0xffffffffu, half ? r0 : r1, 16);
            izT = (half ? z1 : z0) + __shfl_xor_sync(0xffffffffu, half ? z0 : z1, 16);
            inT = (half ? n1 : n0) + __shfl_xor_sync(0xffffffffu, half ? n0 : n1, 16);
        }
        kv = tanh_fast(STAGE(sm + SMF_C));
        ksum = fmaf(2.0f, kv, ksum);
        sm[SMF_B + half * RS + i] = fmaf(dt, kv, hreg);
        __syncthreads();                                             // B3

        // ---- P3: RK4 stage 4 -> h_ode ----
        kv = tanh_fast(STAGE(sm + SMF_B));
        const float hode = fmaf(dt * (1.0f / 6.0f), ksum + kv, hreg);
        sm[SMF_HO + half * RS + i] = hode;
        __syncthreads();                                             // B4

        // ---- P4: GRU W_hh dots (SMEM) + gate combine -> h(t), write A ----
        {
            const ulonglong2* HU = (const ulonglong2*)(sm + SMF_HO + 64 * half);
            const ulonglong2* HV = (const ulonglong2*)(sm + SMF_HO + RS + 64 * half);
            const ulonglong2* W2 = (const ulonglong2*)sm;
            ull R0 = 0, R1 = 0, Z0 = 0, Z1 = 0, N0 = 0, N1 = 0;
#pragma unroll
            for (int q = 0; q < 16; q++) {
                const int idx = (16 * half + q) * 128 + i;
                ulonglong2 wr = W2[idx];
                ulonglong2 wz = W2[4096 + idx];
                ulonglong2 wn = W2[8192 + idx];
                ulonglong2 u = HU[q], v = HV[q];
                fma2(R0, wr.x, u.x); fma2(R0, wr.y, u.y);
                fma2(R1, wr.x, v.x); fma2(R1, wr.y, v.y);
                fma2(Z0, wz.x, u.x); fma2(Z0, wz.y, u.y);
                fma2(Z1, wz.x, v.x); fma2(Z1, wz.y, v.y);
                fma2(N0, wn.x, u.x); fma2(N0, wn.y, u.y);
                fma2(N1, wn.x, v.x); fma2(N1, wn.y, v.y);
            }
            float r0 = psum(R0), r1 = psum(R1);
            float z0 = psum(Z0), z1 = psum(Z1);
            float n0 = psum(N0), n1 = psum(N1);
            float hrT = (half ? r1 : r0) + __shfl_xor_sync(0xffffffffu, half ? r0 : r1, 16);
            float hzT = (half ? z1 : z0) + __shfl_xor_sync(0xffffffffu, half ? z0 : z1, 16);
            float hnT = (half ? n1 : n0) + __shfl_xor_sync(0xffffffffu, half ? n0 : n1, 16);

            float rr = sig_fast(irT + hrT + bs_r);
            float zz = sig_fast(izT + hzT + bs_z);
            float nn = tanh_fast(inT + bihn + rr * (hnT + bhhn));
            hreg = nn + zz * (hode - nn);
            sm[SMF_A + half * RS + i] = hreg;
        }
        __syncthreads();                                             // B5
    }

    // ---- epilogue: out[T-1] from final A ----
    OUTPROJ();
    __syncthreads();
    if (tid < 128) {
        const int base = SMF_XO + (tid >> 6) * 256 + (tid & 63);
        float yf = sm[base] + sm[base + 64] + sm[base + 128] + sm[base + 192] + bo;
        orow[(size_t)(T_ - 1) * DIN] = yf;
    }
}

// ---------------------------------------------------------------------------
extern "C" void kernel_launch(void* const* d_in, const int* in_sizes, int n_in,
                              void* d_out, int out_size)
{
    const float*         x      = (const float*)d_in[0];
    const float*         tp     = (const float*)d_in[1];
    const unsigned char* mask   = (const unsigned char*)d_in[2];
    const float*         W_ih   = (const float*)d_in[3];
    const float*         W_hh   = (const float*)d_in[4];
    const float*         b_ih   = (const float*)d_in[5];
    const float*         b_hh   = (const float*)d_in[6];
    const float*         W_node = (const float*)d_in[7];
    const float*         b_node = (const float*)d_in[8];
    const float*         W_out  = (const float*)d_in[9];
    const float*         b_out  = (const float*)d_in[10];
    float*               out    = (float*)d_out;

    prep_kernel<<<32, 256>>>(W_hh, W_out, mask, tp);

    cudaFuncSetAttribute(enc_gruode_kernel,
                         cudaFuncAttributeMaxDynamicSharedMemorySize,
                         SMEM_BYTES);
    enc_gruode_kernel<<<B_ / 2, 256, SMEM_BYTES>>>(
        x, b_ih, b_hh, W_ih, W_node, b_node, b_out, out);
}